// round 11
// baseline (speedup 1.0000x reference)
#include <cuda_runtime.h>
#include <cuda_bf16.h>
#include <cstdint>

// Problem constants
#define N_TOK   8192        // T*B = 512*16
#define C_DIM   512
#define R_DIM   64          // REDUCE
#define O_DIM   512         // OUT
#define NE      256         // 2^NBITS
#define ROW_LEN 32768       // OUT*REDUCE
#define Y_ELEMS (N_TOK * O_DIM)

// ---------------- device scratch (no allocation allowed) ----------------
__device__ float g_v[N_TOK * R_DIM];     // per-token reduced vector v (t-major)
__device__ int   g_q[N_TOK];             // per-token code qz1
__device__ int   g_hist[NE];
__device__ int   g_start[NE];
__device__ int   g_cursor[NE];
__device__ int   g_order[N_TOK];         // token ids grouped by code

// ---------------- f32x2 helpers (Blackwell packed fp32) ----------------
__device__ __forceinline__ void fma2(unsigned long long &d,
                                     unsigned long long a,
                                     unsigned long long b) {
    asm("fma.rn.f32x2 %0, %1, %2, %0;" : "+l"(d) : "l"(a), "l"(b));
}
__device__ __forceinline__ unsigned long long splat2(float f) {
    unsigned long long r;
    asm("mov.b64 %0, {%1, %1};" : "=l"(r) : "f"(f));
    return r;
}
__device__ __forceinline__ void unpack2(unsigned long long v, float &lo, float &hi) {
    asm("mov.b64 {%0, %1}, %2;" : "=f"(lo), "=f"(hi) : "l"(v));
}

// ---------------- kernel 0: clear histogram ----------------
__global__ void k_init() {
    g_hist[threadIdx.x] = 0;
}

// ---------------- kernel 1: front GEMM ----------------
// Computes, per token t:  v[t, 0..63] = pw_w1 @ x[t]   and the 8 logits
// k_j = map_w[j] @ x[t] + map_b[j]  ->  code bits -> g_q / g_hist.
// Tiled GEMM: 72 rows (64 v + 8 logits) x 64 tokens per block, K=512 in 64-chunks.
// 9 warps: warp w owns 8 rows, each lane owns 2 tokens (f32x2-packed).
__global__ void __launch_bounds__(288) k_front(
        const float* __restrict__ x,
        const float* __restrict__ map_w,
        const float* __restrict__ map_b,
        const float* __restrict__ pw_w1) {
    __shared__ float Xs[64 * 66];   // [k][t], row stride 66 (8B-aligned float2 reads)
    __shared__ float Ws[64 * 74];   // [k][r], row stride 74 (8B-aligned row-pair reads)

    const int tid  = threadIdx.x;
    const int lane = tid & 31;
    const int warp = tid >> 5;               // 0..8
    const int t0   = blockIdx.x * 64;

    unsigned long long accA[4], accB[4];     // rowpair x {tokenA, tokenB}
    #pragma unroll
    for (int i = 0; i < 4; i++) { accA[i] = 0ull; accB[i] = 0ull; }

    for (int c0 = 0; c0 < C_DIM; c0 += 64) {
        if (tid < 256) {
            const int kk = tid & 63;
            const int s4 = tid >> 6;       // 0..3
            #pragma unroll
            for (int t = s4; t < 64; t += 4)
                Xs[kk * 66 + t] = x[(size_t)(t0 + t) * C_DIM + c0 + kk];
            #pragma unroll
            for (int r = s4; r < 72; r += 4) {
                float wv = (r < 64) ? pw_w1[r * C_DIM + c0 + kk]
                                    : map_w[(r - 64) * C_DIM + c0 + kk];
                Ws[kk * 74 + r] = wv;
            }
        }
        __syncthreads();

        #pragma unroll 4
        for (int k = 0; k < 64; k++) {
            float2 xv = *(const float2*)&Xs[k * 66 + 2 * lane];
            unsigned long long xs0 = splat2(xv.x);
            unsigned long long xs1 = splat2(xv.y);
            const float* wrow = &Ws[k * 74 + warp * 8];
            #pragma unroll
            for (int rp = 0; rp < 4; rp++) {
                unsigned long long w2 = *(const unsigned long long*)(wrow + 2 * rp);
                fma2(accA[rp], w2, xs0);
                fma2(accB[rp], w2, xs1);
            }
        }
        __syncthreads();
    }

    // Epilogue. Warps 0..7 hold v rows 0..63; warp 8 holds the 8 logits.
    float* Vt = Xs;                           // reuse: Vt[t][r], stride 65 (4160 <= 4224)
    if (warp < 8) {
        const int tAl = 2 * lane, tBl = 2 * lane + 1;
        #pragma unroll
        for (int rp = 0; rp < 4; rp++) {
            float a0, a1, b0, b1;
            unpack2(accA[rp], a0, a1);
            unpack2(accB[rp], b0, b1);
            int r = warp * 8 + 2 * rp;
            Vt[tAl * 65 + r]     = a0;
            Vt[tAl * 65 + r + 1] = a1;
            Vt[tBl * 65 + r]     = b0;
            Vt[tBl * 65 + r + 1] = b1;
        }
    } else {
        int qA = 0, qB = 0;
        #pragma unroll
        for (int rp = 0; rp < 4; rp++) {
            float a0, a1, b0, b1;
            unpack2(accA[rp], a0, a1);
            unpack2(accB[rp], b0, b1);
            float bias0 = map_b[2 * rp], bias1 = map_b[2 * rp + 1];
            if (a0 + bias0 > 0.f) qA |= 1 << (2 * rp);
            if (a1 + bias1 > 0.f) qA |= 1 << (2 * rp + 1);
            if (b0 + bias0 > 0.f) qB |= 1 << (2 * rp);
            if (b1 + bias1 > 0.f) qB |= 1 << (2 * rp + 1);
        }
        int tA = t0 + 2 * lane;
        g_q[tA]     = qA;
        g_q[tA + 1] = qB;
        atomicAdd(&g_hist[qA], 1);
        atomicAdd(&g_hist[qB], 1);
    }
    __syncthreads();
    // coalesced v write-out
    if (tid < 256) {
        const int r  = tid & 63;
        const int s4 = tid >> 6;
        #pragma unroll
        for (int t = s4; t < 64; t += 4)
            g_v[(size_t)(t0 + t) * R_DIM + r] = Vt[t * 65 + r];
    }
}

// ---------------- kernel 2: exclusive scan over 256 bins ----------------
__global__ void k_scan() {
    __shared__ int s[NE];
    int tid = threadIdx.x;
    int v = g_hist[tid];
    s[tid] = v;
    __syncthreads();
    #pragma unroll
    for (int off = 1; off < NE; off <<= 1) {
        int add = (tid >= off) ? s[tid - off] : 0;
        __syncthreads();
        s[tid] += add;
        __syncthreads();
    }
    int excl = s[tid] - v;
    g_start[tid]  = excl;
    g_cursor[tid] = excl;
}

// ---------------- kernel 3: scatter token ids into bins ----------------
__global__ void k_scatter() {
    int t = blockIdx.x * 256 + threadIdx.x;
    int q = g_q[t];
    int pos = atomicAdd(&g_cursor[q], 1);
    g_order[pos] = t;
}

// ---------------- kernel 4: binned main GEMM ----------------
// For code c (blockIdx.x) and out-tile o0 (blockIdx.y*128):
//   Wsum = w21[c] + w22[255-c]  (tile 128 out x 64 r, transposed into smem)
//   for each token chunk (32): y[tok, o] = Wsum[o,:] . v[tok,:] + bias[o]
// 256 threads, micro-tile 4 out x 4 tokens, token pairs in f32x2.
__global__ void __launch_bounds__(256) k_main(
        const float* __restrict__ w21,
        const float* __restrict__ w22,
        const float* __restrict__ bias,
        float* __restrict__ out) {
    __shared__ float Wsm[64 * 132];  // [r][o], stride 132 (16B-aligned float4)
    __shared__ float Vsm[64 * 36];   // [r][t], stride 36  (16B-aligned float4)

    const int c = blockIdx.x;
    const int n = g_hist[c];
    if (n == 0) return;
    const int start = g_start[c];
    const int o0    = blockIdx.y * 128;
    const int tid   = threadIdx.x;

    {   // load + fuse expert tile (tables read exactly once across grid)
        const float* p1 = w21 + (size_t)c * ROW_LEN + (size_t)o0 * R_DIM;
        const float* p2 = w22 + (size_t)(255 - c) * ROW_LEN + (size_t)o0 * R_DIM;
        const int r  = tid & 63;
        const int os = tid >> 6;
        #pragma unroll
        for (int o = os; o < 128; o += 4)
            Wsm[r * 132 + o] = p1[o * R_DIM + r] + p2[o * R_DIM + r];
    }

    const int ow = tid >> 3;      // 0..31 -> 4 outs each
    const int tg = tid & 7;       // 0..7  -> 4 tokens each
    float b0 = bias[o0 + ow * 4 + 0];
    float b1 = bias[o0 + ow * 4 + 1];
    float b2 = bias[o0 + ow * 4 + 2];
    float b3 = bias[o0 + ow * 4 + 3];

    for (int tb = 0; tb < n; tb += 32) {
        const int nt = min(32, n - tb);
        __syncthreads();
        {   // gather v for up to 32 tokens
            const int r  = tid & 63;
            const int ts = tid >> 6;
            for (int t = ts; t < nt; t += 4) {
                int tok = g_order[start + tb + t];
                Vsm[r * 36 + t] = g_v[(size_t)tok * R_DIM + r];
            }
        }
        __syncthreads();

        unsigned long long acc[4][2];
        #pragma unroll
        for (int i = 0; i < 4; i++) { acc[i][0] = 0ull; acc[i][1] = 0ull; }

        #pragma unroll 8
        for (int r = 0; r < 64; r++) {
            float4 wv = *(const float4*)&Wsm[r * 132 + ow * 4];
            ulonglong2 vv = *(const ulonglong2*)&Vsm[r * 36 + tg * 4];
            unsigned long long w0 = splat2(wv.x);
            unsigned long long w1 = splat2(wv.y);
            unsigned long long w2s = splat2(wv.z);
            unsigned long long w3s = splat2(wv.w);
            fma2(acc[0][0], w0,  vv.x); fma2(acc[0][1], w0,  vv.y);
            fma2(acc[1][0], w1,  vv.x); fma2(acc[1][1], w1,  vv.y);
            fma2(acc[2][0], w2s, vv.x); fma2(acc[2][1], w2s, vv.y);
            fma2(acc[3][0], w3s, vv.x); fma2(acc[3][1], w3s, vv.y);
        }

        #pragma unroll
        for (int tp = 0; tp < 2; tp++) {
            float r0lo, r0hi, r1lo, r1hi, r2lo, r2hi, r3lo, r3hi;
            unpack2(acc[0][tp], r0lo, r0hi);
            unpack2(acc[1][tp], r1lo, r1hi);
            unpack2(acc[2][tp], r2lo, r2hi);
            unpack2(acc[3][tp], r3lo, r3hi);
            int tl = tb + tg * 4 + tp * 2;
            if (tl < n) {
                int tok = g_order[start + tl];
                float4 res = make_float4(r0lo + b0, r1lo + b1, r2lo + b2, r3lo + b3);
                *(float4*)&out[(size_t)tok * O_DIM + o0 + ow * 4] = res;
            }
            if (tl + 1 < n) {
                int tok = g_order[start + tl + 1];
                float4 res = make_float4(r0hi + b0, r1hi + b1, r2hi + b2, r3hi + b3);
                *(float4*)&out[(size_t)tok * O_DIM + o0 + ow * 4] = res;
            }
        }
    }
}

// ---------------- kernel 5: loss + tail padding ----------------
__global__ void k_tail(float* __restrict__ out, int out_size) {
    for (int i = Y_ELEMS + threadIdx.x; i < out_size; i += blockDim.x)
        out[i] = 0.0f;
}

// ---------------- launch ----------------
extern "C" void kernel_launch(void* const* d_in, const int* in_sizes, int n_in,
                              void* d_out, int out_size) {
    const float* x      = (const float*)d_in[0];
    // d_in[1] = key, unused by the forward pass
    const float* map_w  = (const float*)d_in[2];
    const float* map_b  = (const float*)d_in[3];
    const float* pw_w1  = (const float*)d_in[4];
    const float* w21    = (const float*)d_in[5];
    const float* w22    = (const float*)d_in[6];
    const float* pw_B   = (const float*)d_in[7];
    float* out = (float*)d_out;

    k_init<<<1, 256>>>();
    k_front<<<N_TOK / 64, 288>>>(x, map_w, map_b, pw_w1);
    k_scan<<<1, 256>>>();
    k_scatter<<<N_TOK / 256, 256>>>();
    k_main<<<dim3(NE, O_DIM / 128), 256>>>(w21, w22, pw_B, out);
    k_tail<<<1, 256>>>(out, out_size);
}